// round 1
// baseline (speedup 1.0000x reference)
#include <cuda_runtime.h>
#include <math.h>
#include <stdint.h>

// Problem constants: B=4, T=2048, C=1024, H=16, D=64
// q/k/v/ctx scratch: 4*16*2048*64 = 8,388,608 floats each (33.5 MB)
#define QKV_ELEMS (4 * 16 * 2048 * 64)

__device__ float g_q[QKV_ELEMS];
__device__ float g_k[QKV_ELEMS];
__device__ float g_v[QKV_ELEMS];
__device__ float g_ctx[QKV_ELEMS];

// ---------------------------------------------------------------------------
// Kernel 1: QKV projection. x[8192,1024] @ w_qkv[1024,3072] -> scatter into
// g_q/g_k/g_v laid out [B,H,T,D].
// Classic 128x128x8 register-blocked SGEMM, 256 threads, 8x8 per thread.
// ---------------------------------------------------------------------------
__global__ void __launch_bounds__(256) sgemm_qkv_kernel(const float* __restrict__ A,
                                                        const float* __restrict__ W)
{
    const int K = 1024, N = 3072;
    __shared__ float As[8][128];
    __shared__ float Bs[8][128];

    int tid = threadIdx.x;
    int ty = tid >> 4, tx = tid & 15;
    int brow = blockIdx.y * 128;
    int bcol = blockIdx.x * 128;

    float acc[8][8];
#pragma unroll
    for (int i = 0; i < 8; i++)
#pragma unroll
        for (int j = 0; j < 8; j++) acc[i][j] = 0.f;

    int arow_l = tid >> 1, acol_l = (tid & 1) * 4;
    int brow_l = tid >> 5, bcol_l = (tid & 31) * 4;

    const float* Aptr = A + (size_t)(brow + arow_l) * K + acol_l;
    const float* Bptr = W + (size_t)brow_l * N + bcol + bcol_l;

    for (int kt = 0; kt < K; kt += 8) {
        float4 av = *(const float4*)Aptr;
        float4 bv = *(const float4*)Bptr;
        As[acol_l + 0][arow_l] = av.x;
        As[acol_l + 1][arow_l] = av.y;
        As[acol_l + 2][arow_l] = av.z;
        As[acol_l + 3][arow_l] = av.w;
        *(float4*)&Bs[brow_l][bcol_l] = bv;
        __syncthreads();
#pragma unroll
        for (int kk = 0; kk < 8; kk++) {
            float a[8], b[8];
            *(float4*)&a[0] = *(const float4*)&As[kk][ty * 8];
            *(float4*)&a[4] = *(const float4*)&As[kk][ty * 8 + 4];
            *(float4*)&b[0] = *(const float4*)&Bs[kk][tx * 8];
            *(float4*)&b[4] = *(const float4*)&Bs[kk][tx * 8 + 4];
#pragma unroll
            for (int i = 0; i < 8; i++)
#pragma unroll
                for (int j = 0; j < 8; j++) acc[i][j] += a[i] * b[j];
        }
        __syncthreads();
        Aptr += 8;
        Bptr += (size_t)8 * N;
    }

    // Scatter: n -> (which, h, d); m -> (b, t). which is constant per block
    // (bcol is a multiple of 128, 1024 % 128 == 0).
    int which = bcol >> 10;
    float* dst = (which == 0) ? g_q : ((which == 1) ? g_k : g_v);
#pragma unroll
    for (int i = 0; i < 8; i++) {
        int m = brow + ty * 8 + i;
        int bb = m >> 11;
        int t = m & 2047;
#pragma unroll
        for (int j = 0; j < 8; j++) {
            int n = bcol + tx * 8 + j;
            int c = n & 1023;
            int h = c >> 6;
            int d = c & 63;
            dst[((((size_t)bb * 16 + h) * 2048 + t) << 6) + d] = acc[i][j];
        }
    }
}

// ---------------------------------------------------------------------------
// Kernel 2: causal flash attention, fp32.
// grid = (32 q-tiles, 64 b*h). 256 threads as 16x16; each thread owns a 4x4
// S-microtile and 4(q) x 4(d) output microtile. Row softmax stats reduced via
// shfl within 16-lane row groups. P staged in smem for the PV GEMM.
// ---------------------------------------------------------------------------
__global__ void __launch_bounds__(256) attn_kernel()
{
    extern __shared__ float sm[];
    float* Qst = sm;                 // [64 d][68]  (d-major, transposed)
    float* Kst = sm + 64 * 68;       // [64 d][68]
    float* Ps  = sm + 2 * 64 * 68;   // [64 q][68]
    float* Vs  = sm + 3 * 64 * 68;   // [64 k][64]

    int bh = blockIdx.y;             // b*16 + h
    int qt = blockIdx.x;             // query tile (64 rows)
    int h = bh & 15, bb = bh >> 4;

    const float* Qp = g_q + ((size_t)bh * 2048 + qt * 64) * 64;
    const float* Kp = g_k + (size_t)bh * 2048 * 64;
    const float* Vp = g_v + (size_t)bh * 2048 * 64;

    int tid = threadIdx.x;
    int ty = tid >> 4, tx = tid & 15;

    // Load Q tile transposed into smem (d-major).
    {
        int r = tid >> 2;
        int d0 = (tid & 3) * 16;
#pragma unroll
        for (int f = 0; f < 4; f++) {
            float4 qv = *(const float4*)(Qp + r * 64 + d0 + f * 4);
            Qst[(d0 + f * 4 + 0) * 68 + r] = qv.x;
            Qst[(d0 + f * 4 + 1) * 68 + r] = qv.y;
            Qst[(d0 + f * 4 + 2) * 68 + r] = qv.z;
            Qst[(d0 + f * 4 + 3) * 68 + r] = qv.w;
        }
    }

    float m_i[4], l_i[4], o[4][4];
#pragma unroll
    for (int i = 0; i < 4; i++) {
        m_i[i] = -1e30f;
        l_i[i] = 0.f;
#pragma unroll
        for (int j = 0; j < 4; j++) o[i][j] = 0.f;
    }

    const float scale = 0.125f;  // 1/sqrt(64)

    for (int kt = 0; kt <= qt; kt++) {
        __syncthreads();  // protect Kst/Vs/Ps from previous iteration readers
        {
            int r = tid >> 2;
            int d0 = (tid & 3) * 16;
            const float* kr = Kp + (size_t)(kt * 64 + r) * 64 + d0;
            const float* vr = Vp + (size_t)(kt * 64 + r) * 64 + d0;
#pragma unroll
            for (int f = 0; f < 4; f++) {
                float4 kv = *(const float4*)(kr + f * 4);
                Kst[(d0 + f * 4 + 0) * 68 + r] = kv.x;
                Kst[(d0 + f * 4 + 1) * 68 + r] = kv.y;
                Kst[(d0 + f * 4 + 2) * 68 + r] = kv.z;
                Kst[(d0 + f * 4 + 3) * 68 + r] = kv.w;
                *(float4*)&Vs[r * 64 + d0 + f * 4] = *(const float4*)(vr + f * 4);
            }
        }
        __syncthreads();

        // S = Q K^T  (4x4 microtile per thread)
        float s[4][4];
#pragma unroll
        for (int i = 0; i < 4; i++)
#pragma unroll
            for (int j = 0; j < 4; j++) s[i][j] = 0.f;

#pragma unroll 8
        for (int dd = 0; dd < 64; dd++) {
            float4 aq = *(const float4*)&Qst[dd * 68 + ty * 4];
            float4 bk = *(const float4*)&Kst[dd * 68 + tx * 4];
            float a[4] = {aq.x, aq.y, aq.z, aq.w};
            float b[4] = {bk.x, bk.y, bk.z, bk.w};
#pragma unroll
            for (int i = 0; i < 4; i++)
#pragma unroll
                for (int j = 0; j < 4; j++) s[i][j] += a[i] * b[j];
        }

        // scale + causal mask (only the diagonal tile needs masking)
        bool diag = (kt == qt);
#pragma unroll
        for (int i = 0; i < 4; i++) {
            int qi = qt * 64 + ty * 4 + i;
#pragma unroll
            for (int j = 0; j < 4; j++) {
                s[i][j] *= scale;
                if (diag && (kt * 64 + tx * 4 + j > qi)) s[i][j] = -1e30f;
            }
        }

        // online softmax update + stage P
#pragma unroll
        for (int i = 0; i < 4; i++) {
            float mx = fmaxf(fmaxf(s[i][0], s[i][1]), fmaxf(s[i][2], s[i][3]));
#pragma unroll
            for (int w = 1; w < 16; w <<= 1)
                mx = fmaxf(mx, __shfl_xor_sync(0xffffffffu, mx, w));
            float nm = fmaxf(m_i[i], mx);
            float corr = __expf(m_i[i] - nm);
            float sum = 0.f;
#pragma unroll
            for (int j = 0; j < 4; j++) {
                s[i][j] = __expf(s[i][j] - nm);
                sum += s[i][j];
            }
#pragma unroll
            for (int w = 1; w < 16; w <<= 1)
                sum += __shfl_xor_sync(0xffffffffu, sum, w);
            l_i[i] = l_i[i] * corr + sum;
            m_i[i] = nm;
#pragma unroll
            for (int j = 0; j < 4; j++) o[i][j] *= corr;
            *(float4*)&Ps[(ty * 4 + i) * 68 + tx * 4] =
                make_float4(s[i][0], s[i][1], s[i][2], s[i][3]);
        }
        __syncthreads();

        // O += P @ V
#pragma unroll 8
        for (int kk = 0; kk < 64; kk++) {
            float4 bv = *(const float4*)&Vs[kk * 64 + tx * 4];
#pragma unroll
            for (int i = 0; i < 4; i++) {
                float a = Ps[(ty * 4 + i) * 68 + kk];
                o[i][0] += a * bv.x;
                o[i][1] += a * bv.y;
                o[i][2] += a * bv.z;
                o[i][3] += a * bv.w;
            }
        }
    }

    // epilogue: normalize and write ctx in [B,T,C] layout
#pragma unroll
    for (int i = 0; i < 4; i++) {
        float inv = 1.f / l_i[i];
        int qidx = qt * 64 + ty * 4 + i;
        float4 ov = make_float4(o[i][0] * inv, o[i][1] * inv,
                                o[i][2] * inv, o[i][3] * inv);
        *(float4*)&g_ctx[((size_t)bb * 2048 + qidx) * 1024 + h * 64 + tx * 4] = ov;
    }
}

// ---------------------------------------------------------------------------
// Kernel 3: output projection. g_ctx[8192,1024] @ w_out[1024,1024] -> out.
// ---------------------------------------------------------------------------
__global__ void __launch_bounds__(256) sgemm_out_kernel(const float* __restrict__ W,
                                                        float* __restrict__ out)
{
    const int K = 1024, N = 1024;
    __shared__ float As[8][128];
    __shared__ float Bs[8][128];

    int tid = threadIdx.x;
    int ty = tid >> 4, tx = tid & 15;
    int brow = blockIdx.y * 128;
    int bcol = blockIdx.x * 128;

    float acc[8][8];
#pragma unroll
    for (int i = 0; i < 8; i++)
#pragma unroll
        for (int j = 0; j < 8; j++) acc[i][j] = 0.f;

    int arow_l = tid >> 1, acol_l = (tid & 1) * 4;
    int brow_l = tid >> 5, bcol_l = (tid & 31) * 4;

    const float* Aptr = g_ctx + (size_t)(brow + arow_l) * K + acol_l;
    const float* Bptr = W + (size_t)brow_l * N + bcol + bcol_l;

    for (int kt = 0; kt < K; kt += 8) {
        float4 av = *(const float4*)Aptr;
        float4 bv = *(const float4*)Bptr;
        As[acol_l + 0][arow_l] = av.x;
        As[acol_l + 1][arow_l] = av.y;
        As[acol_l + 2][arow_l] = av.z;
        As[acol_l + 3][arow_l] = av.w;
        *(float4*)&Bs[brow_l][bcol_l] = bv;
        __syncthreads();
#pragma unroll
        for (int kk = 0; kk < 8; kk++) {
            float a[8], b[8];
            *(float4*)&a[0] = *(const float4*)&As[kk][ty * 8];
            *(float4*)&a[4] = *(const float4*)&As[kk][ty * 8 + 4];
            *(float4*)&b[0] = *(const float4*)&Bs[kk][tx * 8];
            *(float4*)&b[4] = *(const float4*)&Bs[kk][tx * 8 + 4];
#pragma unroll
            for (int i = 0; i < 8; i++)
#pragma unroll
                for (int j = 0; j < 8; j++) acc[i][j] += a[i] * b[j];
        }
        __syncthreads();
        Aptr += 8;
        Bptr += (size_t)8 * N;
    }

#pragma unroll
    for (int i = 0; i < 8; i++) {
        int m = brow + ty * 8 + i;
#pragma unroll
        for (int j = 0; j < 8; j += 4) {
            int n = bcol + tx * 8 + j;
            *(float4*)&out[(size_t)m * N + n] =
                make_float4(acc[i][j], acc[i][j + 1], acc[i][j + 2], acc[i][j + 3]);
        }
    }
}

// ---------------------------------------------------------------------------
extern "C" void kernel_launch(void* const* d_in, const int* in_sizes, int n_in,
                              void* d_out, int out_size)
{
    const float* x     = (const float*)d_in[0];  // [4,2048,1024]
    const float* w_qkv = (const float*)d_in[1];  // [1024,3072]
    const float* w_out = (const float*)d_in[2];  // [1024,1024]
    float* out = (float*)d_out;                  // [4,2048,1024]

    (void)in_sizes; (void)n_in; (void)out_size;

    // Attention kernel needs 67 KB dynamic smem (> 48 KB static limit).
    const int attn_smem = (3 * 64 * 68 + 64 * 64) * (int)sizeof(float);  // 68608
    cudaFuncSetAttribute(attn_kernel, cudaFuncAttributeMaxDynamicSharedMemorySize,
                         attn_smem);

    // 1) QKV projection: M=8192, N=3072 -> grid (24, 64)
    sgemm_qkv_kernel<<<dim3(24, 64), 256>>>(x, w_qkv);

    // 2) causal flash attention: 32 q-tiles x 64 (b*h)
    attn_kernel<<<dim3(32, 64), 256, attn_smem>>>();

    // 3) output projection: M=8192, N=1024 -> grid (8, 64)
    sgemm_out_kernel<<<dim3(8, 64), 256>>>(w_out, out);
}

// round 5
// speedup vs baseline: 1.7049x; 1.7049x over previous
#include <cuda_runtime.h>
#include <math.h>
#include <stdint.h>

// Problem constants: B=4, T=2048, C=1024, H=16, D=64
#define QKV_ELEMS (4 * 16 * 2048 * 64)

__device__ float g_q[QKV_ELEMS];
__device__ float g_k[QKV_ELEMS];
__device__ float g_v[QKV_ELEMS];
__device__ float g_ctx[QKV_ELEMS];

__device__ __forceinline__ uint32_t f2tf32(float f) {
    uint32_t r;
    asm("cvt.rna.tf32.f32 %0, %1;" : "=r"(r) : "f"(f));
    return r;
}

__device__ __forceinline__ void mma_tf32(float c[4],
                                         uint32_t a0, uint32_t a1, uint32_t a2, uint32_t a3,
                                         uint32_t b0, uint32_t b1) {
    asm volatile(
        "mma.sync.aligned.m16n8k8.row.col.f32.tf32.tf32.f32 "
        "{%0,%1,%2,%3}, {%4,%5,%6,%7}, {%8,%9}, {%0,%1,%2,%3};"
        : "+f"(c[0]), "+f"(c[1]), "+f"(c[2]), "+f"(c[3])
        : "r"(a0), "r"(a1), "r"(a2), "r"(a3), "r"(b0), "r"(b1));
}

// ---------------------------------------------------------------------------
// tf32 tensor-core GEMM: C[M,N] = A[M,K=1024] @ W[1024,N]
// Block tile 128x128, Kchunk 32, 8 warps (2x4), warp tile 64x32.
// SRC_CTX = 1: read A from g_ctx (device global) instead of the A argument.
// EPI = 0: QKV scatter into g_q/g_k/g_v ([B,H,T,D]).  EPI = 1: plain row-major.
// ---------------------------------------------------------------------------
template <int N, int EPI, int SRC_CTX>
__global__ void __launch_bounds__(256) mma_gemm(const float* __restrict__ Ain,
                                                const float* __restrict__ W,
                                                float* __restrict__ out)
{
    const int K = 1024;
    const int LDS = 132;            // padded row stride (floats)
    const int BUF = 32 * LDS;       // 4224
    extern __shared__ uint32_t sh[];
    uint32_t* As = sh;              // 2 * BUF
    uint32_t* Bs = sh + 2 * BUF;    // 2 * BUF

    const float* A = SRC_CTX ? (const float*)g_ctx : Ain;

    int tid = threadIdx.x;
    int lane = tid & 31;
    int wid = tid >> 5;
    int wm = wid & 1;               // 0..1  (64-row slab)
    int wn = wid >> 1;              // 0..3  (32-col slab)
    int brow = blockIdx.y * 128;
    int bcol = blockIdx.x * 128;

    float c[4][4][4];
#pragma unroll
    for (int mt = 0; mt < 4; mt++)
#pragma unroll
        for (int nt = 0; nt < 4; nt++)
#pragma unroll
            for (int e = 0; e < 4; e++) c[mt][nt][e] = 0.f;

    // gmem load mapping
    int a_row = tid >> 3;            // 0..31 (+ i*32)
    int a_c4  = tid & 7;             // float4 within 32-col chunk
    int b_row = tid >> 5;            // 0..7  (+ i*8)
    int b_c4  = tid & 31;            // float4 within 128-col row
    const float* Ap = A + (size_t)(brow + a_row) * K + a_c4 * 4;
    const float* Wp = W + (size_t)b_row * N + bcol + b_c4 * 4;

    float4 ar[4], br[4];

#define LDG_TILE(kt)                                                        \
    {                                                                       \
        const float* ap = Ap + (kt) * 32;                                   \
        const float* wp = Wp + (size_t)(kt) * 32 * N;                       \
        _Pragma("unroll")                                                   \
        for (int i = 0; i < 4; i++) ar[i] = *(const float4*)(ap + (size_t)i * 32 * K); \
        _Pragma("unroll")                                                   \
        for (int i = 0; i < 4; i++) br[i] = *(const float4*)(wp + (size_t)i * 8 * N);  \
    }

#define STS_TILE(p)                                                         \
    {                                                                       \
        uint32_t* as = As + (p) * BUF;                                      \
        uint32_t* bs = Bs + (p) * BUF;                                      \
        _Pragma("unroll")                                                   \
        for (int i = 0; i < 4; i++) {                                       \
            int r = a_row + i * 32;                                         \
            as[(a_c4 * 4 + 0) * LDS + r] = f2tf32(ar[i].x);                 \
            as[(a_c4 * 4 + 1) * LDS + r] = f2tf32(ar[i].y);                 \
            as[(a_c4 * 4 + 2) * LDS + r] = f2tf32(ar[i].z);                 \
            as[(a_c4 * 4 + 3) * LDS + r] = f2tf32(ar[i].w);                 \
        }                                                                   \
        _Pragma("unroll")                                                   \
        for (int i = 0; i < 4; i++) {                                       \
            int r = b_row + i * 8;                                          \
            uint4 t;                                                        \
            t.x = f2tf32(br[i].x); t.y = f2tf32(br[i].y);                   \
            t.z = f2tf32(br[i].z); t.w = f2tf32(br[i].w);                   \
            *(uint4*)&bs[r * LDS + b_c4 * 4] = t;                           \
        }                                                                   \
    }

    LDG_TILE(0);
    STS_TILE(0);
    __syncthreads();

    for (int kt = 0; kt < 32; kt++) {
        int p = kt & 1;
        if (kt + 1 < 32) LDG_TILE(kt + 1);

        const uint32_t* asp = As + p * BUF;
        const uint32_t* bsp = Bs + p * BUF;
        int mrow = wm * 64 + (lane >> 2);
        int ncol = wn * 32 + (lane >> 2);
#pragma unroll
        for (int k8 = 0; k8 < 4; k8++) {
            int k0 = k8 * 8 + (lane & 3);
            uint32_t a[4][4], b[4][2];
#pragma unroll
            for (int mt = 0; mt < 4; mt++) {
                a[mt][0] = asp[k0 * LDS + mrow + mt * 16];
                a[mt][1] = asp[k0 * LDS + mrow + mt * 16 + 8];
                a[mt][2] = asp[(k0 + 4) * LDS + mrow + mt * 16];
                a[mt][3] = asp[(k0 + 4) * LDS + mrow + mt * 16 + 8];
            }
#pragma unroll
            for (int nt = 0; nt < 4; nt++) {
                b[nt][0] = bsp[k0 * LDS + ncol + nt * 8];
                b[nt][1] = bsp[(k0 + 4) * LDS + ncol + nt * 8];
            }
#pragma unroll
            for (int mt = 0; mt < 4; mt++)
#pragma unroll
                for (int nt = 0; nt < 4; nt++)
                    mma_tf32(c[mt][nt], a[mt][0], a[mt][1], a[mt][2], a[mt][3],
                             b[nt][0], b[nt][1]);
        }

        if (kt + 1 < 32) STS_TILE((kt + 1) & 1);
        __syncthreads();
    }
#undef LDG_TILE
#undef STS_TILE

    // epilogue
    int row0 = brow + wm * 64 + (lane >> 2);
    int col0 = bcol + wn * 32 + (lane & 3) * 2;

    if (EPI == 0) {
        // scatter into q/k/v [B,H,T,D]
        int which = bcol >> 10;
        float* dst = (which == 0) ? g_q : ((which == 1) ? g_k : g_v);
#pragma unroll
        for (int mt = 0; mt < 4; mt++) {
#pragma unroll
            for (int nt = 0; nt < 4; nt++) {
                int col = col0 + nt * 8;
                int cc = col & 1023;
                int h = cc >> 6, d = cc & 63;
#pragma unroll
                for (int half = 0; half < 2; half++) {
                    int r = row0 + mt * 16 + half * 8;
                    int bb = r >> 11, t = r & 2047;
                    float2 v;
                    v.x = c[mt][nt][half * 2 + 0];
                    v.y = c[mt][nt][half * 2 + 1];
                    *(float2*)&dst[((((size_t)bb * 16 + h) * 2048 + t) << 6) + d] = v;
                }
            }
        }
    } else {
#pragma unroll
        for (int mt = 0; mt < 4; mt++) {
#pragma unroll
            for (int nt = 0; nt < 4; nt++) {
                int col = col0 + nt * 8;
#pragma unroll
                for (int half = 0; half < 2; half++) {
                    int r = row0 + mt * 16 + half * 8;
                    float2 v;
                    v.x = c[mt][nt][half * 2 + 0];
                    v.y = c[mt][nt][half * 2 + 1];
                    *(float2*)&out[(size_t)r * N + col] = v;
                }
            }
        }
    }
}

// ---------------------------------------------------------------------------
// Kernel 2: causal flash attention, fp32 (unchanged from R1).
// ---------------------------------------------------------------------------
__global__ void __launch_bounds__(256) attn_kernel()
{
    extern __shared__ float sm[];
    float* Qst = sm;                 // [64 d][68]
    float* Kst = sm + 64 * 68;       // [64 d][68]
    float* Ps  = sm + 2 * 64 * 68;   // [64 q][68]
    float* Vs  = sm + 3 * 64 * 68;   // [64 k][64]

    int bh = blockIdx.y;
    int qt = blockIdx.x;
    int h = bh & 15, bb = bh >> 4;

    const float* Qp = g_q + ((size_t)bh * 2048 + qt * 64) * 64;
    const float* Kp = g_k + (size_t)bh * 2048 * 64;
    const float* Vp = g_v + (size_t)bh * 2048 * 64;

    int tid = threadIdx.x;
    int ty = tid >> 4, tx = tid & 15;

    {
        int r = tid >> 2;
        int d0 = (tid & 3) * 16;
#pragma unroll
        for (int f = 0; f < 4; f++) {
            float4 qv = *(const float4*)(Qp + r * 64 + d0 + f * 4);
            Qst[(d0 + f * 4 + 0) * 68 + r] = qv.x;
            Qst[(d0 + f * 4 + 1) * 68 + r] = qv.y;
            Qst[(d0 + f * 4 + 2) * 68 + r] = qv.z;
            Qst[(d0 + f * 4 + 3) * 68 + r] = qv.w;
        }
    }

    float m_i[4], l_i[4], o[4][4];
#pragma unroll
    for (int i = 0; i < 4; i++) {
        m_i[i] = -1e30f;
        l_i[i] = 0.f;
#pragma unroll
        for (int j = 0; j < 4; j++) o[i][j] = 0.f;
    }

    const float scale = 0.125f;

    for (int kt = 0; kt <= qt; kt++) {
        __syncthreads();
        {
            int r = tid >> 2;
            int d0 = (tid & 3) * 16;
            const float* kr = Kp + (size_t)(kt * 64 + r) * 64 + d0;
            const float* vr = Vp + (size_t)(kt * 64 + r) * 64 + d0;
#pragma unroll
            for (int f = 0; f < 4; f++) {
                float4 kv = *(const float4*)(kr + f * 4);
                Kst[(d0 + f * 4 + 0) * 68 + r] = kv.x;
                Kst[(d0 + f * 4 + 1) * 68 + r] = kv.y;
                Kst[(d0 + f * 4 + 2) * 68 + r] = kv.z;
                Kst[(d0 + f * 4 + 3) * 68 + r] = kv.w;
                *(float4*)&Vs[r * 64 + d0 + f * 4] = *(const float4*)(vr + f * 4);
            }
        }
        __syncthreads();

        float s[4][4];
#pragma unroll
        for (int i = 0; i < 4; i++)
#pragma unroll
            for (int j = 0; j < 4; j++) s[i][j] = 0.f;

#pragma unroll 8
        for (int dd = 0; dd < 64; dd++) {
            float4 aq = *(const float4*)&Qst[dd * 68 + ty * 4];
            float4 bk = *(const float4*)&Kst[dd * 68 + tx * 4];
            float a[4] = {aq.x, aq.y, aq.z, aq.w};
            float b[4] = {bk.x, bk.y, bk.z, bk.w};
#pragma unroll
            for (int i = 0; i < 4; i++)
#pragma unroll
                for (int j = 0; j < 4; j++) s[i][j] += a[i] * b[j];
        }

        bool diag = (kt == qt);
#pragma unroll
        for (int i = 0; i < 4; i++) {
            int qi = qt * 64 + ty * 4 + i;
#pragma unroll
            for (int j = 0; j < 4; j++) {
                s[i][j] *= scale;
                if (diag && (kt * 64 + tx * 4 + j > qi)) s[i][j] = -1e30f;
            }
        }

#pragma unroll
        for (int i = 0; i < 4; i++) {
            float mx = fmaxf(fmaxf(s[i][0], s[i][1]), fmaxf(s[i][2], s[i][3]));
#pragma unroll
            for (int w = 1; w < 16; w <<= 1)
                mx = fmaxf(mx, __shfl_xor_sync(0xffffffffu, mx, w));
            float nm = fmaxf(m_i[i], mx);
            float corr = __expf(m_i[i] - nm);
            float sum = 0.f;
#pragma unroll
            for (int j = 0; j < 4; j++) {
                s[i][j] = __expf(s[i][j] - nm);
                sum += s[i][j];
            }
#pragma unroll
            for (int w = 1; w < 16; w <<= 1)
                sum += __shfl_xor_sync(0xffffffffu, sum, w);
            l_i[i] = l_i[i] * corr + sum;
            m_i[i] = nm;
#pragma unroll
            for (int j = 0; j < 4; j++) o[i][j] *= corr;
            *(float4*)&Ps[(ty * 4 + i) * 68 + tx * 4] =
                make_float4(s[i][0], s[i][1], s[i][2], s[i][3]);
        }
        __syncthreads();

#pragma unroll 8
        for (int kk = 0; kk < 64; kk++) {
            float4 bv = *(const float4*)&Vs[kk * 64 + tx * 4];
#pragma unroll
            for (int i = 0; i < 4; i++) {
                float a = Ps[(ty * 4 + i) * 68 + kk];
                o[i][0] += a * bv.x;
                o[i][1] += a * bv.y;
                o[i][2] += a * bv.z;
                o[i][3] += a * bv.w;
            }
        }
    }

#pragma unroll
    for (int i = 0; i < 4; i++) {
        float inv = 1.f / l_i[i];
        int qidx = qt * 64 + ty * 4 + i;
        float4 ov = make_float4(o[i][0] * inv, o[i][1] * inv,
                                o[i][2] * inv, o[i][3] * inv);
        *(float4*)&g_ctx[((size_t)bb * 2048 + qidx) * 1024 + h * 64 + tx * 4] = ov;
    }
}

// ---------------------------------------------------------------------------
extern "C" void kernel_launch(void* const* d_in, const int* in_sizes, int n_in,
                              void* d_out, int out_size)
{
    const float* x     = (const float*)d_in[0];  // [4,2048,1024]
    const float* w_qkv = (const float*)d_in[1];  // [1024,3072]
    const float* w_out = (const float*)d_in[2];  // [1024,1024]
    float* out = (float*)d_out;                  // [4,2048,1024]

    (void)in_sizes; (void)n_in; (void)out_size;

    const int gemm_smem = 4 * 32 * 132 * (int)sizeof(float);  // 67584
    const int attn_smem = (3 * 64 * 68 + 64 * 64) * (int)sizeof(float);  // 68608

    cudaFuncSetAttribute(mma_gemm<3072, 0, 0>,
                         cudaFuncAttributeMaxDynamicSharedMemorySize, gemm_smem);
    cudaFuncSetAttribute(mma_gemm<1024, 1, 1>,
                         cudaFuncAttributeMaxDynamicSharedMemorySize, gemm_smem);
    cudaFuncSetAttribute(attn_kernel,
                         cudaFuncAttributeMaxDynamicSharedMemorySize, attn_smem);

    // 1) QKV projection: M=8192, N=3072
    mma_gemm<3072, 0, 0><<<dim3(24, 64), 256, gemm_smem>>>(x, w_qkv, nullptr);

    // 2) causal flash attention
    attn_kernel<<<dim3(32, 64), 256, attn_smem>>>();

    // 3) output projection: M=8192, N=1024 (A = g_ctx, read device-side)
    mma_gemm<1024, 1, 1><<<dim3(8, 64), 256, gemm_smem>>>(nullptr, w_out, out);
}

// round 6
// speedup vs baseline: 2.5283x; 1.4829x over previous
#include <cuda_runtime.h>
#include <math.h>
#include <stdint.h>

// Problem constants: B=4, T=2048, C=1024, H=16, D=64
#define QKV_ELEMS (4 * 16 * 2048 * 64)

__device__ float g_q[QKV_ELEMS];
__device__ float g_k[QKV_ELEMS];
__device__ float g_v[QKV_ELEMS];
__device__ float g_ctx[QKV_ELEMS];

__device__ __forceinline__ uint32_t f2tf32(float f) {
    uint32_t r;
    asm("cvt.rna.tf32.f32 %0, %1;" : "=r"(r) : "f"(f));
    return r;
}

__device__ __forceinline__ void mma_tf32(float c[4],
                                         uint32_t a0, uint32_t a1, uint32_t a2, uint32_t a3,
                                         uint32_t b0, uint32_t b1) {
    asm volatile(
        "mma.sync.aligned.m16n8k8.row.col.f32.tf32.tf32.f32 "
        "{%0,%1,%2,%3}, {%4,%5,%6,%7}, {%8,%9}, {%0,%1,%2,%3};"
        : "+f"(c[0]), "+f"(c[1]), "+f"(c[2]), "+f"(c[3])
        : "r"(a0), "r"(a1), "r"(a2), "r"(a3), "r"(b0), "r"(b1));
}

// ---------------------------------------------------------------------------
// tf32 tensor-core GEMM: C[M,N] = A[M,K=1024] @ W[1024,N]  (unchanged from R5)
// ---------------------------------------------------------------------------
template <int N, int EPI, int SRC_CTX>
__global__ void __launch_bounds__(256) mma_gemm(const float* __restrict__ Ain,
                                                const float* __restrict__ W,
                                                float* __restrict__ out)
{
    const int K = 1024;
    const int LDS = 132;
    const int BUF = 32 * LDS;
    extern __shared__ uint32_t sh[];
    uint32_t* As = sh;
    uint32_t* Bs = sh + 2 * BUF;

    const float* A = SRC_CTX ? (const float*)g_ctx : Ain;

    int tid = threadIdx.x;
    int lane = tid & 31;
    int wid = tid >> 5;
    int wm = wid & 1;
    int wn = wid >> 1;
    int brow = blockIdx.y * 128;
    int bcol = blockIdx.x * 128;

    float c[4][4][4];
#pragma unroll
    for (int mt = 0; mt < 4; mt++)
#pragma unroll
        for (int nt = 0; nt < 4; nt++)
#pragma unroll
            for (int e = 0; e < 4; e++) c[mt][nt][e] = 0.f;

    int a_row = tid >> 3;
    int a_c4  = tid & 7;
    int b_row = tid >> 5;
    int b_c4  = tid & 31;
    const float* Ap = A + (size_t)(brow + a_row) * K + a_c4 * 4;
    const float* Wp = W + (size_t)b_row * N + bcol + b_c4 * 4;

    float4 ar[4], br[4];

#define LDG_TILE(kt)                                                        \
    {                                                                       \
        const float* ap = Ap + (kt) * 32;                                   \
        const float* wp = Wp + (size_t)(kt) * 32 * N;                       \
        _Pragma("unroll")                                                   \
        for (int i = 0; i < 4; i++) ar[i] = *(const float4*)(ap + (size_t)i * 32 * K); \
        _Pragma("unroll")                                                   \
        for (int i = 0; i < 4; i++) br[i] = *(const float4*)(wp + (size_t)i * 8 * N);  \
    }

#define STS_TILE(p)                                                         \
    {                                                                       \
        uint32_t* as = As + (p) * BUF;                                      \
        uint32_t* bs = Bs + (p) * BUF;                                      \
        _Pragma("unroll")                                                   \
        for (int i = 0; i < 4; i++) {                                       \
            int r = a_row + i * 32;                                         \
            as[(a_c4 * 4 + 0) * LDS + r] = f2tf32(ar[i].x);                 \
            as[(a_c4 * 4 + 1) * LDS + r] = f2tf32(ar[i].y);                 \
            as[(a_c4 * 4 + 2) * LDS + r] = f2tf32(ar[i].z);                 \
            as[(a_c4 * 4 + 3) * LDS + r] = f2tf32(ar[i].w);                 \
        }                                                                   \
        _Pragma("unroll")                                                   \
        for (int i = 0; i < 4; i++) {                                       \
            int r = b_row + i * 8;                                          \
            uint4 t;                                                        \
            t.x = f2tf32(br[i].x); t.y = f2tf32(br[i].y);                   \
            t.z = f2tf32(br[i].z); t.w = f2tf32(br[i].w);                   \
            *(uint4*)&bs[r * LDS + b_c4 * 4] = t;                           \
        }                                                                   \
    }

    LDG_TILE(0);
    STS_TILE(0);
    __syncthreads();

    for (int kt = 0; kt < 32; kt++) {
        int p = kt & 1;
        if (kt + 1 < 32) LDG_TILE(kt + 1);

        const uint32_t* asp = As + p * BUF;
        const uint32_t* bsp = Bs + p * BUF;
        int mrow = wm * 64 + (lane >> 2);
        int ncol = wn * 32 + (lane >> 2);
#pragma unroll
        for (int k8 = 0; k8 < 4; k8++) {
            int k0 = k8 * 8 + (lane & 3);
            uint32_t a[4][4], b[4][2];
#pragma unroll
            for (int mt = 0; mt < 4; mt++) {
                a[mt][0] = asp[k0 * LDS + mrow + mt * 16];
                a[mt][1] = asp[k0 * LDS + mrow + mt * 16 + 8];
                a[mt][2] = asp[(k0 + 4) * LDS + mrow + mt * 16];
                a[mt][3] = asp[(k0 + 4) * LDS + mrow + mt * 16 + 8];
            }
#pragma unroll
            for (int nt = 0; nt < 4; nt++) {
                b[nt][0] = bsp[k0 * LDS + ncol + nt * 8];
                b[nt][1] = bsp[(k0 + 4) * LDS + ncol + nt * 8];
            }
#pragma unroll
            for (int mt = 0; mt < 4; mt++)
#pragma unroll
                for (int nt = 0; nt < 4; nt++)
                    mma_tf32(c[mt][nt], a[mt][0], a[mt][1], a[mt][2], a[mt][3],
                             b[nt][0], b[nt][1]);
        }

        if (kt + 1 < 32) STS_TILE((kt + 1) & 1);
        __syncthreads();
    }
#undef LDG_TILE
#undef STS_TILE

    int row0 = brow + wm * 64 + (lane >> 2);
    int col0 = bcol + wn * 32 + (lane & 3) * 2;

    if (EPI == 0) {
        int which = bcol >> 10;
        float* dst = (which == 0) ? g_q : ((which == 1) ? g_k : g_v);
#pragma unroll
        for (int mt = 0; mt < 4; mt++) {
#pragma unroll
            for (int nt = 0; nt < 4; nt++) {
                int col = col0 + nt * 8;
                int cc = col & 1023;
                int h = cc >> 6, d = cc & 63;
#pragma unroll
                for (int half = 0; half < 2; half++) {
                    int r = row0 + mt * 16 + half * 8;
                    int bb = r >> 11, t = r & 2047;
                    float2 v;
                    v.x = c[mt][nt][half * 2 + 0];
                    v.y = c[mt][nt][half * 2 + 1];
                    *(float2*)&dst[((((size_t)bb * 16 + h) * 2048 + t) << 6) + d] = v;
                }
            }
        }
    } else {
#pragma unroll
        for (int mt = 0; mt < 4; mt++) {
#pragma unroll
            for (int nt = 0; nt < 4; nt++) {
                int col = col0 + nt * 8;
#pragma unroll
                for (int half = 0; half < 2; half++) {
                    int r = row0 + mt * 16 + half * 8;
                    float2 v;
                    v.x = c[mt][nt][half * 2 + 0];
                    v.y = c[mt][nt][half * 2 + 1];
                    *(float2*)&out[(size_t)r * N + col] = v;
                }
            }
        }
    }
}

// ---------------------------------------------------------------------------
// Kernel 2: causal flash attention with tf32 tensor-core MMAs.
// grid = (32 q-tiles [reversed], 64 b*h), 256 threads = 8 warps (4 m x 2 n).
// Warp tile: 16(q) x 32 for both S = Q K^T and O += P V.
// smem (uint32 words): Qs[64][68] tf32, Ks[64][68] tf32 ([key][d]),
//                      Vst[64][68] tf32 ([d][key]), Ss[64][68] f32 S / tf32 P,
//                      stats: m[64], l[64], corr[64].
// ---------------------------------------------------------------------------
__global__ void __launch_bounds__(256) attn_mma_kernel()
{
    extern __shared__ uint32_t sm[];
    const int LDW = 68;
    uint32_t* Qs  = sm;
    uint32_t* Ks  = sm + 64 * LDW;
    uint32_t* Vst = sm + 2 * 64 * LDW;
    uint32_t* Ss  = sm + 3 * 64 * LDW;
    float* sm_m    = (float*)(sm + 4 * 64 * LDW);
    float* sm_l    = sm_m + 64;
    float* sm_corr = sm_m + 128;

    int bh = blockIdx.y;
    int qt = gridDim.x - 1 - blockIdx.x;   // heavy tiles first
    int h = bh & 15, bb = bh >> 4;

    const float* Qp = g_q + ((size_t)bh * 2048 + qt * 64) * 64;
    const float* Kp = g_k + (size_t)bh * 2048 * 64;
    const float* Vp = g_v + (size_t)bh * 2048 * 64;

    int tid = threadIdx.x;
    int lane = tid & 31;
    int wid = tid >> 5;
    int wm = wid & 3;          // m-tile: rows 16*wm
    int wn = wid >> 2;         // n-half: cols 32*wn
    int g = lane >> 2;         // group id (0..7)
    int t = lane & 3;          // thread-in-group

    // Load Q tile once: row r = tid>>2, cols (tid&3)*16..+15
    {
        int r = tid >> 2;
        int c0 = (tid & 3) * 16;
        const float* qr = Qp + r * 64 + c0;
#pragma unroll
        for (int f = 0; f < 4; f++) {
            float4 v = *(const float4*)(qr + f * 4);
            Qs[r * LDW + c0 + f * 4 + 0] = f2tf32(v.x);
            Qs[r * LDW + c0 + f * 4 + 1] = f2tf32(v.y);
            Qs[r * LDW + c0 + f * 4 + 2] = f2tf32(v.z);
            Qs[r * LDW + c0 + f * 4 + 3] = f2tf32(v.w);
        }
    }
    if (tid < 64) {
        sm_m[tid] = -1e30f;
        sm_l[tid] = 0.f;
    }

    // O accumulators: rows {16*wm+g, +8}, cols 32*wn + nt*8 + 2t + {0,1}
    float o[4][4];
#pragma unroll
    for (int nt = 0; nt < 4; nt++)
#pragma unroll
        for (int e = 0; e < 4; e++) o[nt][e] = 0.f;

    const float scale = 0.125f;  // 1/sqrt(64)

    for (int kt = 0; kt <= qt; kt++) {
        __syncthreads();   // prior iter's PV reads done; Q/stat init visible
        // Load K (row-major) and V (transposed) as tf32
        {
            int r = tid >> 2;
            int c0 = (tid & 3) * 16;
            const float* kr = Kp + (size_t)(kt * 64 + r) * 64 + c0;
            const float* vr = Vp + (size_t)(kt * 64 + r) * 64 + c0;
#pragma unroll
            for (int f = 0; f < 4; f++) {
                float4 kv = *(const float4*)(kr + f * 4);
                float4 vv = *(const float4*)(vr + f * 4);
                Ks[r * LDW + c0 + f * 4 + 0] = f2tf32(kv.x);
                Ks[r * LDW + c0 + f * 4 + 1] = f2tf32(kv.y);
                Ks[r * LDW + c0 + f * 4 + 2] = f2tf32(kv.z);
                Ks[r * LDW + c0 + f * 4 + 3] = f2tf32(kv.w);
                Vst[(c0 + f * 4 + 0) * LDW + r] = f2tf32(vv.x);
                Vst[(c0 + f * 4 + 1) * LDW + r] = f2tf32(vv.y);
                Vst[(c0 + f * 4 + 2) * LDW + r] = f2tf32(vv.z);
                Vst[(c0 + f * 4 + 3) * LDW + r] = f2tf32(vv.w);
            }
        }
        __syncthreads();

        // S = Q K^T   (warp: m16 x n32, K-dim = 64 = 8 k-steps)
        float cs[4][4];
#pragma unroll
        for (int nt = 0; nt < 4; nt++)
#pragma unroll
            for (int e = 0; e < 4; e++) cs[nt][e] = 0.f;

        int arow = 16 * wm + g;
#pragma unroll
        for (int kk = 0; kk < 8; kk++) {
            int k0 = kk * 8 + t;
            uint32_t a0 = Qs[arow * LDW + k0];
            uint32_t a1 = Qs[(arow + 8) * LDW + k0];
            uint32_t a2 = Qs[arow * LDW + k0 + 4];
            uint32_t a3 = Qs[(arow + 8) * LDW + k0 + 4];
#pragma unroll
            for (int nt = 0; nt < 4; nt++) {
                int n = 32 * wn + nt * 8 + g;
                uint32_t b0 = Ks[n * LDW + k0];
                uint32_t b1 = Ks[n * LDW + k0 + 4];
                mma_tf32(cs[nt], a0, a1, a2, a3, b0, b1);
            }
        }

        // store scaled S (f32) to Ss
#pragma unroll
        for (int nt = 0; nt < 4; nt++) {
            int col = 32 * wn + nt * 8 + 2 * t;
            *(float2*)&Ss[arow * LDW + col] =
                make_float2(cs[nt][0] * scale, cs[nt][1] * scale);
            *(float2*)&Ss[(arow + 8) * LDW + col] =
                make_float2(cs[nt][2] * scale, cs[nt][3] * scale);
        }
        __syncthreads();

        // softmax: 4 threads per row (tid>>2 = row, tid&3 = 16-col chunk)
        {
            int r = tid >> 2;
            int c0 = (tid & 3) * 16;
            float* row = (float*)&Ss[r * LDW];
            bool diag = (kt == qt);
            float v[16];
#pragma unroll
            for (int f = 0; f < 4; f++) {
                float4 x = *(float4*)&row[c0 + f * 4];
                v[f * 4 + 0] = x.x; v[f * 4 + 1] = x.y;
                v[f * 4 + 2] = x.z; v[f * 4 + 3] = x.w;
            }
            if (diag) {
#pragma unroll
                for (int j = 0; j < 16; j++)
                    if (c0 + j > r) v[j] = -1e30f;
            }
            float mx = v[0];
#pragma unroll
            for (int j = 1; j < 16; j++) mx = fmaxf(mx, v[j]);
            mx = fmaxf(mx, __shfl_xor_sync(0xffffffffu, mx, 1));
            mx = fmaxf(mx, __shfl_xor_sync(0xffffffffu, mx, 2));
            float mprev = sm_m[r];
            float nm = fmaxf(mprev, mx);
            float sum = 0.f;
#pragma unroll
            for (int j = 0; j < 16; j++) {
                v[j] = __expf(v[j] - nm);
                sum += v[j];
            }
            // write P as tf32 bits (in place)
#pragma unroll
            for (int j = 0; j < 16; j++)
                Ss[r * LDW + c0 + j] = f2tf32(v[j]);
            sum += __shfl_xor_sync(0xffffffffu, sum, 1);
            sum += __shfl_xor_sync(0xffffffffu, sum, 2);
            if ((tid & 3) == 0) {
                float corr = __expf(mprev - nm);
                sm_l[r] = sm_l[r] * corr + sum;
                sm_m[r] = nm;
                sm_corr[r] = corr;
            }
        }
        __syncthreads();

        // O scale + O += P V
        {
            float cr0 = sm_corr[arow];
            float cr1 = sm_corr[arow + 8];
#pragma unroll
            for (int nt = 0; nt < 4; nt++) {
                o[nt][0] *= cr0; o[nt][1] *= cr0;
                o[nt][2] *= cr1; o[nt][3] *= cr1;
            }
#pragma unroll
            for (int kk = 0; kk < 8; kk++) {
                int k0 = kk * 8 + t;
                uint32_t a0 = Ss[arow * LDW + k0];
                uint32_t a1 = Ss[(arow + 8) * LDW + k0];
                uint32_t a2 = Ss[arow * LDW + k0 + 4];
                uint32_t a3 = Ss[(arow + 8) * LDW + k0 + 4];
#pragma unroll
                for (int nt = 0; nt < 4; nt++) {
                    int n = 32 * wn + nt * 8 + g;    // d index
                    uint32_t b0 = Vst[n * LDW + k0];
                    uint32_t b1 = Vst[n * LDW + k0 + 4];
                    mma_tf32(o[nt], a0, a1, a2, a3, b0, b1);
                }
            }
        }
    }

    // epilogue: normalize rows, write to g_ctx [B,T,C]
    {
        int arow = 16 * wm + g;
        float il0 = 1.f / sm_l[arow];
        float il1 = 1.f / sm_l[arow + 8];
        int q0 = qt * 64 + arow;
#pragma unroll
        for (int nt = 0; nt < 4; nt++) {
            int dcol = 32 * wn + nt * 8 + 2 * t;
            *(float2*)&g_ctx[((size_t)bb * 2048 + q0) * 1024 + h * 64 + dcol] =
                make_float2(o[nt][0] * il0, o[nt][1] * il0);
            *(float2*)&g_ctx[((size_t)bb * 2048 + q0 + 8) * 1024 + h * 64 + dcol] =
                make_float2(o[nt][2] * il1, o[nt][3] * il1);
        }
    }
}

// ---------------------------------------------------------------------------
extern "C" void kernel_launch(void* const* d_in, const int* in_sizes, int n_in,
                              void* d_out, int out_size)
{
    const float* x     = (const float*)d_in[0];  // [4,2048,1024]
    const float* w_qkv = (const float*)d_in[1];  // [1024,3072]
    const float* w_out = (const float*)d_in[2];  // [1024,1024]
    float* out = (float*)d_out;                  // [4,2048,1024]

    (void)in_sizes; (void)n_in; (void)out_size;

    const int gemm_smem = 4 * 32 * 132 * (int)sizeof(float);          // 67584
    const int attn_smem = (4 * 64 * 68 + 192) * (int)sizeof(float);   // 70400

    cudaFuncSetAttribute(mma_gemm<3072, 0, 0>,
                         cudaFuncAttributeMaxDynamicSharedMemorySize, gemm_smem);
    cudaFuncSetAttribute(mma_gemm<1024, 1, 1>,
                         cudaFuncAttributeMaxDynamicSharedMemorySize, gemm_smem);
    cudaFuncSetAttribute(attn_mma_kernel,
                         cudaFuncAttributeMaxDynamicSharedMemorySize, attn_smem);

    // 1) QKV projection: M=8192, N=3072
    mma_gemm<3072, 0, 0><<<dim3(24, 64), 256, gemm_smem>>>(x, w_qkv, nullptr);

    // 2) causal flash attention (tf32 tensor cores)
    attn_mma_kernel<<<dim3(32, 64), 256, attn_smem>>>();

    // 3) output projection: M=8192, N=1024 (A = g_ctx, read device-side)
    mma_gemm<1024, 1, 1><<<dim3(8, 64), 256, gemm_smem>>>(nullptr, w_out, out);
}

// round 9
// speedup vs baseline: 2.9028x; 1.1481x over previous
#include <cuda_runtime.h>
#include <math.h>
#include <stdint.h>

// Problem constants: B=4, T=2048, C=1024, H=16, D=64
#define QKV_ELEMS (4 * 16 * 2048 * 64)

__device__ float g_q[QKV_ELEMS];
__device__ float g_k[QKV_ELEMS];
__device__ float g_v[QKV_ELEMS];
__device__ float g_ctx[QKV_ELEMS];

__device__ __forceinline__ uint32_t f2tf32(float f) {
    uint32_t r;
    asm("cvt.rna.tf32.f32 %0, %1;" : "=r"(r) : "f"(f));
    return r;
}

__device__ __forceinline__ void mma_tf32(float c[4],
                                         uint32_t a0, uint32_t a1, uint32_t a2, uint32_t a3,
                                         uint32_t b0, uint32_t b1) {
    asm volatile(
        "mma.sync.aligned.m16n8k8.row.col.f32.tf32.tf32.f32 "
        "{%0,%1,%2,%3}, {%4,%5,%6,%7}, {%8,%9}, {%0,%1,%2,%3};"
        : "+f"(c[0]), "+f"(c[1]), "+f"(c[2]), "+f"(c[3])
        : "r"(a0), "r"(a1), "r"(a2), "r"(a3), "r"(b0), "r"(b1));
}

// ---------------------------------------------------------------------------
// tf32 tensor-core GEMM: C[M,N] = A[M,K=1024] @ W[1024,N]
// Block tile 128x128, Kchunk 32, 8 warps (2x4), warp tile 64x32.
// Conflict-free staging: A as [row][k] stride 36 words, B as [n][k] stride 36.
//   - MMA operand LDS: bank = 4g + t  -> 32 distinct banks
//   - A/B STS float4:  per-phase distinct 16B banks
// SRC_CTX=1: A = g_ctx. EPI=0: scatter q/k/v. EPI=1: row-major out.
// ---------------------------------------------------------------------------
template <int N, int EPI, int SRC_CTX>
__global__ void __launch_bounds__(256) mma_gemm(const float* __restrict__ Ain,
                                                const float* __restrict__ W,
                                                float* __restrict__ out)
{
    const int K = 1024;
    const int LDK = 36;             // padded k-stride (words); 36 mod 32 = 4
    const int BUF = 128 * LDK;      // 4608 words per operand buffer
    extern __shared__ uint32_t sh[];
    uint32_t* As = sh;              // 2 * BUF
    uint32_t* Bs = sh + 2 * BUF;    // 2 * BUF

    const float* A = SRC_CTX ? (const float*)g_ctx : Ain;

    int tid = threadIdx.x;
    int lane = tid & 31;
    int wid = tid >> 5;
    int wm = wid & 1;               // 64-row slab
    int wn = wid >> 1;              // 32-col slab
    int brow = blockIdx.y * 128;
    int bcol = blockIdx.x * 128;

    float c[4][4][4];
#pragma unroll
    for (int mt = 0; mt < 4; mt++)
#pragma unroll
        for (int nt = 0; nt < 4; nt++)
#pragma unroll
            for (int e = 0; e < 4; e++) c[mt][nt][e] = 0.f;

    // A staging: 1024 float4 = 128 rows x 8 c4 chunks; thread does 4
    int a_r0 = tid >> 3;            // +i*32
    int a_c4 = tid & 7;
    // B staging: n = tid&127, k-subblock (tid>>7)*16
    int bn  = tid & 127;
    int bkb = (tid >> 7) * 16;

    const float* Ap = A + (size_t)(brow + a_r0) * K + a_c4 * 4;
    const float* Wp = W + bcol + bn;

    float4 ar[4];
    float bv[16];

#define LDG_TILE(kt)                                                         \
    {                                                                        \
        int k0 = (kt) * 32;                                                  \
        _Pragma("unroll")                                                    \
        for (int i = 0; i < 4; i++)                                          \
            ar[i] = *(const float4*)(Ap + k0 + (size_t)i * 32 * K);          \
        _Pragma("unroll")                                                    \
        for (int j = 0; j < 16; j++)                                         \
            bv[j] = Wp[(size_t)(k0 + bkb + j) * N];                          \
    }

#define STS_TILE(p)                                                          \
    {                                                                        \
        uint32_t* as = As + (p) * BUF;                                       \
        uint32_t* bs = Bs + (p) * BUF;                                       \
        _Pragma("unroll")                                                    \
        for (int i = 0; i < 4; i++) {                                        \
            uint4 t;                                                         \
            t.x = f2tf32(ar[i].x); t.y = f2tf32(ar[i].y);                    \
            t.z = f2tf32(ar[i].z); t.w = f2tf32(ar[i].w);                    \
            *(uint4*)&as[(a_r0 + i * 32) * LDK + a_c4 * 4] = t;              \
        }                                                                    \
        _Pragma("unroll")                                                    \
        for (int j = 0; j < 4; j++) {                                        \
            uint4 t;                                                         \
            t.x = f2tf32(bv[j * 4 + 0]); t.y = f2tf32(bv[j * 4 + 1]);        \
            t.z = f2tf32(bv[j * 4 + 2]); t.w = f2tf32(bv[j * 4 + 3]);        \
            *(uint4*)&bs[bn * LDK + bkb + j * 4] = t;                        \
        }                                                                    \
    }

    LDG_TILE(0);
    STS_TILE(0);
    __syncthreads();

    int mrow = wm * 64 + (lane >> 2);
    int ncol = wn * 32 + (lane >> 2);
    int tk = lane & 3;

    for (int kt = 0; kt < 32; kt++) {
        int p = kt & 1;
        if (kt + 1 < 32) LDG_TILE(kt + 1);

        const uint32_t* asp = As + p * BUF;
        const uint32_t* bsp = Bs + p * BUF;
#pragma unroll
        for (int k8 = 0; k8 < 4; k8++) {
            int k0 = k8 * 8 + tk;
            uint32_t a[4][4], b[4][2];
#pragma unroll
            for (int mt = 0; mt < 4; mt++) {
                int r = mrow + mt * 16;
                a[mt][0] = asp[r * LDK + k0];
                a[mt][1] = asp[(r + 8) * LDK + k0];
                a[mt][2] = asp[r * LDK + k0 + 4];
                a[mt][3] = asp[(r + 8) * LDK + k0 + 4];
            }
#pragma unroll
            for (int nt = 0; nt < 4; nt++) {
                int n = ncol + nt * 8;
                b[nt][0] = bsp[n * LDK + k0];
                b[nt][1] = bsp[n * LDK + k0 + 4];
            }
#pragma unroll
            for (int mt = 0; mt < 4; mt++)
#pragma unroll
                for (int nt = 0; nt < 4; nt++)
                    mma_tf32(c[mt][nt], a[mt][0], a[mt][1], a[mt][2], a[mt][3],
                             b[nt][0], b[nt][1]);
        }

        if (kt + 1 < 32) STS_TILE((kt + 1) & 1);
        __syncthreads();
    }
#undef LDG_TILE
#undef STS_TILE

    // epilogue (identical to R6 layout)
    int row0 = brow + wm * 64 + (lane >> 2);
    int col0 = bcol + wn * 32 + (lane & 3) * 2;

    if (EPI == 0) {
        int which = bcol >> 10;
        float* dst = (which == 0) ? g_q : ((which == 1) ? g_k : g_v);
#pragma unroll
        for (int mt = 0; mt < 4; mt++) {
#pragma unroll
            for (int nt = 0; nt < 4; nt++) {
                int col = col0 + nt * 8;
                int cc = col & 1023;
                int h = cc >> 6, d = cc & 63;
#pragma unroll
                for (int half = 0; half < 2; half++) {
                    int r = row0 + mt * 16 + half * 8;
                    int bb = r >> 11, t = r & 2047;
                    float2 v;
                    v.x = c[mt][nt][half * 2 + 0];
                    v.y = c[mt][nt][half * 2 + 1];
                    *(float2*)&dst[((((size_t)bb * 16 + h) * 2048 + t) << 6) + d] = v;
                }
            }
        }
    } else {
#pragma unroll
        for (int mt = 0; mt < 4; mt++) {
#pragma unroll
            for (int nt = 0; nt < 4; nt++) {
                int col = col0 + nt * 8;
#pragma unroll
                for (int half = 0; half < 2; half++) {
                    int r = row0 + mt * 16 + half * 8;
                    float2 v;
                    v.x = c[mt][nt][half * 2 + 0];
                    v.y = c[mt][nt][half * 2 + 1];
                    *(float2*)&out[(size_t)r * N + col] = v;
                }
            }
        }
    }
}

// ---------------------------------------------------------------------------
// causal flash attention with tf32 mma.sync (unchanged from R6 — passing)
// ---------------------------------------------------------------------------
__global__ void __launch_bounds__(256) attn_mma_kernel()
{
    extern __shared__ uint32_t sm[];
    const int LDW = 68;
    uint32_t* Qs  = sm;
    uint32_t* Ks  = sm + 64 * LDW;
    uint32_t* Vst = sm + 2 * 64 * LDW;
    uint32_t* Ss  = sm + 3 * 64 * LDW;
    float* sm_m    = (float*)(sm + 4 * 64 * LDW);
    float* sm_l    = sm_m + 64;
    float* sm_corr = sm_m + 128;

    int bh = blockIdx.y;
    int qt = gridDim.x - 1 - blockIdx.x;
    int h = bh & 15, bb = bh >> 4;

    const float* Qp = g_q + ((size_t)bh * 2048 + qt * 64) * 64;
    const float* Kp = g_k + (size_t)bh * 2048 * 64;
    const float* Vp = g_v + (size_t)bh * 2048 * 64;

    int tid = threadIdx.x;
    int lane = tid & 31;
    int wid = tid >> 5;
    int wm = wid & 3;
    int wn = wid >> 2;
    int g = lane >> 2;
    int t = lane & 3;

    {
        int r = tid >> 2;
        int c0 = (tid & 3) * 16;
        const float* qr = Qp + r * 64 + c0;
#pragma unroll
        for (int f = 0; f < 4; f++) {
            float4 v = *(const float4*)(qr + f * 4);
            Qs[r * LDW + c0 + f * 4 + 0] = f2tf32(v.x);
            Qs[r * LDW + c0 + f * 4 + 1] = f2tf32(v.y);
            Qs[r * LDW + c0 + f * 4 + 2] = f2tf32(v.z);
            Qs[r * LDW + c0 + f * 4 + 3] = f2tf32(v.w);
        }
    }
    if (tid < 64) {
        sm_m[tid] = -1e30f;
        sm_l[tid] = 0.f;
    }

    float o[4][4];
#pragma unroll
    for (int nt = 0; nt < 4; nt++)
#pragma unroll
        for (int e = 0; e < 4; e++) o[nt][e] = 0.f;

    const float scale = 0.125f;

    for (int kt = 0; kt <= qt; kt++) {
        __syncthreads();
        {
            int r = tid >> 2;
            int c0 = (tid & 3) * 16;
            const float* kr = Kp + (size_t)(kt * 64 + r) * 64 + c0;
            const float* vr = Vp + (size_t)(kt * 64 + r) * 64 + c0;
#pragma unroll
            for (int f = 0; f < 4; f++) {
                float4 kv = *(const float4*)(kr + f * 4);
                float4 vv = *(const float4*)(vr + f * 4);
                Ks[r * LDW + c0 + f * 4 + 0] = f2tf32(kv.x);
                Ks[r * LDW + c0 + f * 4 + 1] = f2tf32(kv.y);
                Ks[r * LDW + c0 + f * 4 + 2] = f2tf32(kv.z);
                Ks[r * LDW + c0 + f * 4 + 3] = f2tf32(kv.w);
                Vst[(c0 + f * 4 + 0) * LDW + r] = f2tf32(vv.x);
                Vst[(c0 + f * 4 + 1) * LDW + r] = f2tf32(vv.y);
                Vst[(c0 + f * 4 + 2) * LDW + r] = f2tf32(vv.z);
                Vst[(c0 + f * 4 + 3) * LDW + r] = f2tf32(vv.w);
            }
        }
        __syncthreads();

        float cs[4][4];
#pragma unroll
        for (int nt = 0; nt < 4; nt++)
#pragma unroll
            for (int e = 0; e < 4; e++) cs[nt][e] = 0.f;

        int arow = 16 * wm + g;
#pragma unroll
        for (int kk = 0; kk < 8; kk++) {
            int k0 = kk * 8 + t;
            uint32_t a0 = Qs[arow * LDW + k0];
            uint32_t a1 = Qs[(arow + 8) * LDW + k0];
            uint32_t a2 = Qs[arow * LDW + k0 + 4];
            uint32_t a3 = Qs[(arow + 8) * LDW + k0 + 4];
#pragma unroll
            for (int nt = 0; nt < 4; nt++) {
                int n = 32 * wn + nt * 8 + g;
                uint32_t b0 = Ks[n * LDW + k0];
                uint32_t b1 = Ks[n * LDW + k0 + 4];
                mma_tf32(cs[nt], a0, a1, a2, a3, b0, b1);
            }
        }

#pragma unroll
        for (int nt = 0; nt < 4; nt++) {
            int col = 32 * wn + nt * 8 + 2 * t;
            *(float2*)&Ss[arow * LDW + col] =
                make_float2(cs[nt][0] * scale, cs[nt][1] * scale);
            *(float2*)&Ss[(arow + 8) * LDW + col] =
                make_float2(cs[nt][2] * scale, cs[nt][3] * scale);
        }
        __syncthreads();

        {
            int r = tid >> 2;
            int c0 = (tid & 3) * 16;
            float* row = (float*)&Ss[r * LDW];
            bool diag = (kt == qt);
            float v[16];
#pragma unroll
            for (int f = 0; f < 4; f++) {
                float4 x = *(float4*)&row[c0 + f * 4];
                v[f * 4 + 0] = x.x; v[f * 4 + 1] = x.y;
                v[f * 4 + 2] = x.z; v[f * 4 + 3] = x.w;
            }
            if (diag) {
#pragma unroll
                for (int j = 0; j < 16; j++)
                    if (c0 + j > r) v[j] = -1e30f;
            }
            float mx = v[0];
#pragma unroll
            for (int j = 1; j < 16; j++) mx = fmaxf(mx, v[j]);
            mx = fmaxf(mx, __shfl_xor_sync(0xffffffffu, mx, 1));
            mx = fmaxf(mx, __shfl_xor_sync(0xffffffffu, mx, 2));
            float mprev = sm_m[r];
            float nm = fmaxf(mprev, mx);
            float sum = 0.f;
#pragma unroll
            for (int j = 0; j < 16; j++) {
                v[j] = __expf(v[j] - nm);
                sum += v[j];
            }
#pragma unroll
            for (int j = 0; j < 16; j++)
                Ss[r * LDW + c0 + j] = f2tf32(v[j]);
            sum += __shfl_xor_sync(0xffffffffu, sum, 1);
            sum += __shfl_xor_sync(0xffffffffu, sum, 2);
            if ((tid & 3) == 0) {
                float corr = __expf(mprev - nm);
                sm_l[r] = sm_l[r] * corr + sum;
                sm_m[r] = nm;
                sm_corr[r] = corr;
            }
        }
        __syncthreads();

        {
            float cr0 = sm_corr[arow];
            float cr1 = sm_corr[arow + 8];
#pragma unroll
            for (int nt = 0; nt < 4; nt++) {
                o[nt][0] *= cr0; o[nt][1] *= cr0;
                o[nt][2] *= cr1; o[nt][3] *= cr1;
            }
#pragma unroll
            for (int kk = 0; kk < 8; kk++) {
                int k0 = kk * 8 + t;
                uint32_t a0 = Ss[arow * LDW + k0];
                uint32_t a1 = Ss[(arow + 8) * LDW + k0];
                uint32_t a2 = Ss[arow * LDW + k0 + 4];
                uint32_t a3 = Ss[(arow + 8) * LDW + k0 + 4];
#pragma unroll
                for (int nt = 0; nt < 4; nt++) {
                    int n = 32 * wn + nt * 8 + g;
                    uint32_t b0 = Vst[n * LDW + k0];
                    uint32_t b1 = Vst[n * LDW + k0 + 4];
                    mma_tf32(o[nt], a0, a1, a2, a3, b0, b1);
                }
            }
        }
    }

    {
        int arow = 16 * wm + g;
        float il0 = 1.f / sm_l[arow];
        float il1 = 1.f / sm_l[arow + 8];
        int q0 = qt * 64 + arow;
#pragma unroll
        for (int nt = 0; nt < 4; nt++) {
            int dcol = 32 * wn + nt * 8 + 2 * t;
            *(float2*)&g_ctx[((size_t)bb * 2048 + q0) * 1024 + h * 64 + dcol] =
                make_float2(o[nt][0] * il0, o[nt][1] * il0);
            *(float2*)&g_ctx[((size_t)bb * 2048 + q0 + 8) * 1024 + h * 64 + dcol] =
                make_float2(o[nt][2] * il1, o[nt][3] * il1);
        }
    }
}

// ---------------------------------------------------------------------------
extern "C" void kernel_launch(void* const* d_in, const int* in_sizes, int n_in,
                              void* d_out, int out_size)
{
    const float* x     = (const float*)d_in[0];  // [4,2048,1024]
    const float* w_qkv = (const float*)d_in[1];  // [1024,3072]
    const float* w_out = (const float*)d_in[2];  // [1024,1024]
    float* out = (float*)d_out;                  // [4,2048,1024]

    (void)in_sizes; (void)n_in; (void)out_size;

    const int gemm_smem = 4 * 128 * 36 * (int)sizeof(float);          // 73728
    const int attn_smem = (4 * 64 * 68 + 192) * (int)sizeof(float);   // 70400

    cudaFuncSetAttribute(mma_gemm<3072, 0, 0>,
                         cudaFuncAttributeMaxDynamicSharedMemorySize, gemm_smem);
    cudaFuncSetAttribute(mma_gemm<1024, 1, 1>,
                         cudaFuncAttributeMaxDynamicSharedMemorySize, gemm_smem);
    cudaFuncSetAttribute(attn_mma_kernel,
                         cudaFuncAttributeMaxDynamicSharedMemorySize, attn_smem);

    // 1) QKV projection: M=8192, N=3072
    mma_gemm<3072, 0, 0><<<dim3(24, 64), 256, gemm_smem>>>(x, w_qkv, nullptr);

    // 2) causal flash attention (tf32 mma.sync)
    attn_mma_kernel<<<dim3(32, 64), 256, attn_smem>>>();

    // 3) output projection: M=8192, N=1024 (A = g_ctx, read device-side)
    mma_gemm<1024, 1, 1><<<dim3(8, 64), 256, gemm_smem>>>(nullptr, w_out, out);
}

// round 10
// speedup vs baseline: 3.5960x; 1.2388x over previous
#include <cuda_runtime.h>
#include <cuda_fp16.h>
#include <math.h>
#include <stdint.h>

// Problem constants: B=4, T=2048, C=1024, H=16, D=64
#define QKV_ELEMS (4 * 16 * 2048 * 64)

__device__ float g_q[QKV_ELEMS];
__device__ float g_k[QKV_ELEMS];
__device__ float g_v[QKV_ELEMS];
__device__ float g_ctx[QKV_ELEMS];

__device__ __forceinline__ uint32_t f2tf32(float f) {
    uint32_t r;
    asm("cvt.rna.tf32.f32 %0, %1;" : "=r"(r) : "f"(f));
    return r;
}

__device__ __forceinline__ uint32_t pack2h(float a, float b) {
    half2 h = __floats2half2_rn(a, b);   // low = a, high = b
    return *reinterpret_cast<uint32_t*>(&h);
}

__device__ __forceinline__ void mma_tf32(float c[4],
                                         uint32_t a0, uint32_t a1, uint32_t a2, uint32_t a3,
                                         uint32_t b0, uint32_t b1) {
    asm volatile(
        "mma.sync.aligned.m16n8k8.row.col.f32.tf32.tf32.f32 "
        "{%0,%1,%2,%3}, {%4,%5,%6,%7}, {%8,%9}, {%0,%1,%2,%3};"
        : "+f"(c[0]), "+f"(c[1]), "+f"(c[2]), "+f"(c[3])
        : "r"(a0), "r"(a1), "r"(a2), "r"(a3), "r"(b0), "r"(b1));
}

__device__ __forceinline__ void mma_f16(float c[4],
                                        uint32_t a0, uint32_t a1, uint32_t a2, uint32_t a3,
                                        uint32_t b0, uint32_t b1) {
    asm volatile(
        "mma.sync.aligned.m16n8k16.row.col.f32.f16.f16.f32 "
        "{%0,%1,%2,%3}, {%4,%5,%6,%7}, {%8,%9}, {%0,%1,%2,%3};"
        : "+f"(c[0]), "+f"(c[1]), "+f"(c[2]), "+f"(c[3])
        : "r"(a0), "r"(a1), "r"(a2), "r"(a3), "r"(b0), "r"(b1));
}

// ---------------------------------------------------------------------------
// tf32 tensor-core GEMM (unchanged from R9 — passing, conflict-free staging)
// ---------------------------------------------------------------------------
template <int N, int EPI, int SRC_CTX>
__global__ void __launch_bounds__(256) mma_gemm(const float* __restrict__ Ain,
                                                const float* __restrict__ W,
                                                float* __restrict__ out)
{
    const int K = 1024;
    const int LDK = 36;
    const int BUF = 128 * LDK;
    extern __shared__ uint32_t sh[];
    uint32_t* As = sh;
    uint32_t* Bs = sh + 2 * BUF;

    const float* A = SRC_CTX ? (const float*)g_ctx : Ain;

    int tid = threadIdx.x;
    int lane = tid & 31;
    int wid = tid >> 5;
    int wm = wid & 1;
    int wn = wid >> 1;
    int brow = blockIdx.y * 128;
    int bcol = blockIdx.x * 128;

    float c[4][4][4];
#pragma unroll
    for (int mt = 0; mt < 4; mt++)
#pragma unroll
        for (int nt = 0; nt < 4; nt++)
#pragma unroll
            for (int e = 0; e < 4; e++) c[mt][nt][e] = 0.f;

    int a_r0 = tid >> 3;
    int a_c4 = tid & 7;
    int bn  = tid & 127;
    int bkb = (tid >> 7) * 16;

    const float* Ap = A + (size_t)(brow + a_r0) * K + a_c4 * 4;
    const float* Wp = W + bcol + bn;

    float4 ar[4];
    float bv[16];

#define LDG_TILE(kt)                                                         \
    {                                                                        \
        int k0 = (kt) * 32;                                                  \
        _Pragma("unroll")                                                    \
        for (int i = 0; i < 4; i++)                                          \
            ar[i] = *(const float4*)(Ap + k0 + (size_t)i * 32 * K);          \
        _Pragma("unroll")                                                    \
        for (int j = 0; j < 16; j++)                                         \
            bv[j] = Wp[(size_t)(k0 + bkb + j) * N];                          \
    }

#define STS_TILE(p)                                                          \
    {                                                                        \
        uint32_t* as = As + (p) * BUF;                                       \
        uint32_t* bs = Bs + (p) * BUF;                                       \
        _Pragma("unroll")                                                    \
        for (int i = 0; i < 4; i++) {                                        \
            uint4 t;                                                         \
            t.x = f2tf32(ar[i].x); t.y = f2tf32(ar[i].y);                    \
            t.z = f2tf32(ar[i].z); t.w = f2tf32(ar[i].w);                    \
            *(uint4*)&as[(a_r0 + i * 32) * LDK + a_c4 * 4] = t;              \
        }                                                                    \
        _Pragma("unroll")                                                    \
        for (int j = 0; j < 4; j++) {                                        \
            uint4 t;                                                         \
            t.x = f2tf32(bv[j * 4 + 0]); t.y = f2tf32(bv[j * 4 + 1]);        \
            t.z = f2tf32(bv[j * 4 + 2]); t.w = f2tf32(bv[j * 4 + 3]);        \
            *(uint4*)&bs[bn * LDK + bkb + j * 4] = t;                        \
        }                                                                    \
    }

    LDG_TILE(0);
    STS_TILE(0);
    __syncthreads();

    int mrow = wm * 64 + (lane >> 2);
    int ncol = wn * 32 + (lane >> 2);
    int tk = lane & 3;

    for (int kt = 0; kt < 32; kt++) {
        int p = kt & 1;
        if (kt + 1 < 32) LDG_TILE(kt + 1);

        const uint32_t* asp = As + p * BUF;
        const uint32_t* bsp = Bs + p * BUF;
#pragma unroll
        for (int k8 = 0; k8 < 4; k8++) {
            int k0 = k8 * 8 + tk;
            uint32_t a[4][4], b[4][2];
#pragma unroll
            for (int mt = 0; mt < 4; mt++) {
                int r = mrow + mt * 16;
                a[mt][0] = asp[r * LDK + k0];
                a[mt][1] = asp[(r + 8) * LDK + k0];
                a[mt][2] = asp[r * LDK + k0 + 4];
                a[mt][3] = asp[(r + 8) * LDK + k0 + 4];
            }
#pragma unroll
            for (int nt = 0; nt < 4; nt++) {
                int n = ncol + nt * 8;
                b[nt][0] = bsp[n * LDK + k0];
                b[nt][1] = bsp[n * LDK + k0 + 4];
            }
#pragma unroll
            for (int mt = 0; mt < 4; mt++)
#pragma unroll
                for (int nt = 0; nt < 4; nt++)
                    mma_tf32(c[mt][nt], a[mt][0], a[mt][1], a[mt][2], a[mt][3],
                             b[nt][0], b[nt][1]);
        }

        if (kt + 1 < 32) STS_TILE((kt + 1) & 1);
        __syncthreads();
    }
#undef LDG_TILE
#undef STS_TILE

    int row0 = brow + wm * 64 + (lane >> 2);
    int col0 = bcol + wn * 32 + (lane & 3) * 2;

    if (EPI == 0) {
        int which = bcol >> 10;
        float* dst = (which == 0) ? g_q : ((which == 1) ? g_k : g_v);
#pragma unroll
        for (int mt = 0; mt < 4; mt++) {
#pragma unroll
            for (int nt = 0; nt < 4; nt++) {
                int col = col0 + nt * 8;
                int cc = col & 1023;
                int h = cc >> 6, d = cc & 63;
#pragma unroll
                for (int half = 0; half < 2; half++) {
                    int r = row0 + mt * 16 + half * 8;
                    int bb = r >> 11, t = r & 2047;
                    float2 v;
                    v.x = c[mt][nt][half * 2 + 0];
                    v.y = c[mt][nt][half * 2 + 1];
                    *(float2*)&dst[((((size_t)bb * 16 + h) * 2048 + t) << 6) + d] = v;
                }
            }
        }
    } else {
#pragma unroll
        for (int mt = 0; mt < 4; mt++) {
#pragma unroll
            for (int nt = 0; nt < 4; nt++) {
                int col = col0 + nt * 8;
#pragma unroll
                for (int half = 0; half < 2; half++) {
                    int r = row0 + mt * 16 + half * 8;
                    float2 v;
                    v.x = c[mt][nt][half * 2 + 0];
                    v.y = c[mt][nt][half * 2 + 1];
                    *(float2*)&out[(size_t)r * N + col] = v;
                }
            }
        }
    }
}

// ---------------------------------------------------------------------------
// Causal flash attention, fp16 tensor cores (m16n8k16), fp32 softmax.
// grid = (32 q-tiles [reversed], 64 b*h), 8 warps (4m x 2n), warp tile 16x32.
// smem words: Qh[64][36] h2(k=d), Kh[64][36] h2(k=d), Vt[64][36] h2(k=key,
// rows=d), Ph[64][36] h2(k=key), Ss f32 [64][68], stats 192.
// All fragment loads: bank = 4g + t -> conflict-free.
// ---------------------------------------------------------------------------
__global__ void __launch_bounds__(256) attn_h_kernel()
{
    extern __shared__ uint32_t sm[];
    const int LDH = 36;
    uint32_t* Qh = sm;                       // 2304
    uint32_t* Kh = sm + 2304;
    uint32_t* Vt = sm + 4608;
    uint32_t* Ph = sm + 6912;
    float*    Ss = (float*)(sm + 9216);      // [64][68] f32
    float* sm_m    = (float*)(sm + 13568);
    float* sm_l    = sm_m + 64;
    float* sm_corr = sm_m + 128;

    int bh = blockIdx.y;
    int qt = gridDim.x - 1 - blockIdx.x;
    int h = bh & 15, bb = bh >> 4;

    const float* Qp = g_q + ((size_t)bh * 2048 + qt * 64) * 64;
    const float* Kp = g_k + (size_t)bh * 2048 * 64;
    const float* Vp = g_v + (size_t)bh * 2048 * 64;

    int tid = threadIdx.x;
    int lane = tid & 31;
    int wid = tid >> 5;
    int wm = wid & 3;
    int wn = wid >> 2;
    int g = lane >> 2;
    int t = lane & 3;

    int r4 = tid >> 2;         // staging row (0..63)
    int c4 = tid & 3;          // 16-float chunk

    // Q staging (once): pack along d
    {
        const float* qr = Qp + r4 * 64 + c4 * 16;
        uint32_t w[8];
#pragma unroll
        for (int f = 0; f < 4; f++) {
            float4 v = *(const float4*)(qr + f * 4);
            w[2 * f + 0] = pack2h(v.x, v.y);
            w[2 * f + 1] = pack2h(v.z, v.w);
        }
        *(uint4*)&Qh[r4 * LDH + c4 * 8]     = *(uint4*)&w[0];
        *(uint4*)&Qh[r4 * LDH + c4 * 8 + 4] = *(uint4*)&w[4];
    }
    if (tid < 64) {
        sm_m[tid] = -1e30f;
        sm_l[tid] = 0.f;
    }

    float o[4][4];
#pragma unroll
    for (int nt = 0; nt < 4; nt++)
#pragma unroll
        for (int e = 0; e < 4; e++) o[nt][e] = 0.f;

    const float scale = 0.125f;
    int arow = 16 * wm + g;

    // V staging mapping: key-pair kp = 4*warp + (lane&3), d = (lane>>2) + 8j
    int v_kp = 4 * wid + (lane & 3);
    int v_d0 = lane >> 2;

    for (int kt = 0; kt <= qt; kt++) {
        __syncthreads();
        // K staging: pack along d (rows = keys)
        {
            const float* kr = Kp + (size_t)(kt * 64 + r4) * 64 + c4 * 16;
            uint32_t w[8];
#pragma unroll
            for (int f = 0; f < 4; f++) {
                float4 v = *(const float4*)(kr + f * 4);
                w[2 * f + 0] = pack2h(v.x, v.y);
                w[2 * f + 1] = pack2h(v.z, v.w);
            }
            *(uint4*)&Kh[r4 * LDH + c4 * 8]     = *(uint4*)&w[0];
            *(uint4*)&Kh[r4 * LDH + c4 * 8 + 4] = *(uint4*)&w[4];
        }
        // V staging: transposed, pack along key
        {
            const float* v0p = Vp + (size_t)(kt * 64 + 2 * v_kp) * 64;
            const float* v1p = v0p + 64;
#pragma unroll
            for (int j = 0; j < 8; j++) {
                int d = v_d0 + 8 * j;
                Vt[d * LDH + v_kp] = pack2h(v0p[d], v1p[d]);
            }
        }
        __syncthreads();

        // S = Q K^T  (fp16 m16n8k16, 4 k-steps over d=64)
        float cs[4][4];
#pragma unroll
        for (int nt = 0; nt < 4; nt++)
#pragma unroll
            for (int e = 0; e < 4; e++) cs[nt][e] = 0.f;

#pragma unroll
        for (int ks = 0; ks < 4; ks++) {
            int k0 = ks * 8 + t;
            uint32_t a0 = Qh[arow * LDH + k0];
            uint32_t a1 = Qh[(arow + 8) * LDH + k0];
            uint32_t a2 = Qh[arow * LDH + k0 + 4];
            uint32_t a3 = Qh[(arow + 8) * LDH + k0 + 4];
#pragma unroll
            for (int nt = 0; nt < 4; nt++) {
                int n = 32 * wn + nt * 8 + g;
                uint32_t b0 = Kh[n * LDH + k0];
                uint32_t b1 = Kh[n * LDH + k0 + 4];
                mma_f16(cs[nt], a0, a1, a2, a3, b0, b1);
            }
        }

#pragma unroll
        for (int nt = 0; nt < 4; nt++) {
            int col = 32 * wn + nt * 8 + 2 * t;
            *(float2*)&Ss[arow * 68 + col] =
                make_float2(cs[nt][0] * scale, cs[nt][1] * scale);
            *(float2*)&Ss[(arow + 8) * 68 + col] =
                make_float2(cs[nt][2] * scale, cs[nt][3] * scale);
        }
        __syncthreads();

        // softmax (fp32), write P as packed half2
        {
            int r = r4;
            int c0 = c4 * 16;
            float* row = &Ss[r * 68];
            bool diag = (kt == qt);
            float v[16];
#pragma unroll
            for (int f = 0; f < 4; f++) {
                float4 x = *(float4*)&row[c0 + f * 4];
                v[f * 4 + 0] = x.x; v[f * 4 + 1] = x.y;
                v[f * 4 + 2] = x.z; v[f * 4 + 3] = x.w;
            }
            if (diag) {
#pragma unroll
                for (int j = 0; j < 16; j++)
                    if (c0 + j > r) v[j] = -1e30f;
            }
            float mx = v[0];
#pragma unroll
            for (int j = 1; j < 16; j++) mx = fmaxf(mx, v[j]);
            mx = fmaxf(mx, __shfl_xor_sync(0xffffffffu, mx, 1));
            mx = fmaxf(mx, __shfl_xor_sync(0xffffffffu, mx, 2));
            float mprev = sm_m[r];
            float nm = fmaxf(mprev, mx);
            float sum = 0.f;
#pragma unroll
            for (int j = 0; j < 16; j++) {
                v[j] = __expf(v[j] - nm);
                sum += v[j];
            }
            uint32_t pw[8];
#pragma unroll
            for (int j = 0; j < 8; j++)
                pw[j] = pack2h(v[2 * j], v[2 * j + 1]);
            *(uint4*)&Ph[r * LDH + c4 * 8]     = *(uint4*)&pw[0];
            *(uint4*)&Ph[r * LDH + c4 * 8 + 4] = *(uint4*)&pw[4];
            sum += __shfl_xor_sync(0xffffffffu, sum, 1);
            sum += __shfl_xor_sync(0xffffffffu, sum, 2);
            if (c4 == 0) {
                float corr = __expf(mprev - nm);
                sm_l[r] = sm_l[r] * corr + sum;
                sm_m[r] = nm;
                sm_corr[r] = corr;
            }
        }
        __syncthreads();

        // O = O*corr + P V  (fp16, 4 k-steps over 64 keys)
        {
            float cr0 = sm_corr[arow];
            float cr1 = sm_corr[arow + 8];
#pragma unroll
            for (int nt = 0; nt < 4; nt++) {
                o[nt][0] *= cr0; o[nt][1] *= cr0;
                o[nt][2] *= cr1; o[nt][3] *= cr1;
            }
#pragma unroll
            for (int ks = 0; ks < 4; ks++) {
                int k0 = ks * 8 + t;
                uint32_t a0 = Ph[arow * LDH + k0];
                uint32_t a1 = Ph[(arow + 8) * LDH + k0];
                uint32_t a2 = Ph[arow * LDH + k0 + 4];
                uint32_t a3 = Ph[(arow + 8) * LDH + k0 + 4];
#pragma unroll
                for (int nt = 0; nt < 4; nt++) {
                    int n = 32 * wn + nt * 8 + g;    // d index
                    uint32_t b0 = Vt[n * LDH + k0];
                    uint32_t b1 = Vt[n * LDH + k0 + 4];
                    mma_f16(o[nt], a0, a1, a2, a3, b0, b1);
                }
            }
        }
    }

    // epilogue: normalize, write g_ctx [B,T,C]
    {
        float il0 = 1.f / sm_l[arow];
        float il1 = 1.f / sm_l[arow + 8];
        int q0 = qt * 64 + arow;
#pragma unroll
        for (int nt = 0; nt < 4; nt++) {
            int dcol = 32 * wn + nt * 8 + 2 * t;
            *(float2*)&g_ctx[((size_t)bb * 2048 + q0) * 1024 + h * 64 + dcol] =
                make_float2(o[nt][0] * il0, o[nt][1] * il0);
            *(float2*)&g_ctx[((size_t)bb * 2048 + q0 + 8) * 1024 + h * 64 + dcol] =
                make_float2(o[nt][2] * il1, o[nt][3] * il1);
        }
    }
}

// ---------------------------------------------------------------------------
extern "C" void kernel_launch(void* const* d_in, const int* in_sizes, int n_in,
                              void* d_out, int out_size)
{
    const float* x     = (const float*)d_in[0];  // [4,2048,1024]
    const float* w_qkv = (const float*)d_in[1];  // [1024,3072]
    const float* w_out = (const float*)d_in[2];  // [1024,1024]
    float* out = (float*)d_out;                  // [4,2048,1024]

    (void)in_sizes; (void)n_in; (void)out_size;

    const int gemm_smem = 4 * 128 * 36 * (int)sizeof(float);   // 73728
    const int attn_smem = 13760 * (int)sizeof(uint32_t);       // 55040

    cudaFuncSetAttribute(mma_gemm<3072, 0, 0>,
                         cudaFuncAttributeMaxDynamicSharedMemorySize, gemm_smem);
    cudaFuncSetAttribute(mma_gemm<1024, 1, 1>,
                         cudaFuncAttributeMaxDynamicSharedMemorySize, gemm_smem);
    cudaFuncSetAttribute(attn_h_kernel,
                         cudaFuncAttributeMaxDynamicSharedMemorySize, attn_smem);

    // 1) QKV projection: M=8192, N=3072
    mma_gemm<3072, 0, 0><<<dim3(24, 64), 256, gemm_smem>>>(x, w_qkv, nullptr);

    // 2) causal flash attention (fp16 tensor cores)
    attn_h_kernel<<<dim3(32, 64), 256, attn_smem>>>();

    // 3) output projection: M=8192, N=1024 (A = g_ctx, read device-side)
    mma_gemm<1024, 1, 1><<<dim3(8, 64), 256, gemm_smem>>>(nullptr, w_out, out);
}